// round 11
// baseline (speedup 1.0000x reference)
#include <cuda_runtime.h>
#include <cuda_fp16.h>
#include <math.h>
#include <stdint.h>

// Problem constants
#define BB 4
#define SS 2048
#define HH 16
#define DMODEL 1024
#define DK 64
#define MM (BB*SS)            // 8192

// ---------------- scratch (__device__ globals: allocation-guard safe) ------
__device__ float  g_q[(size_t)MM*DMODEL];      // [B,S,D] fp32
__device__ float  g_k[(size_t)MM*DMODEL];
__device__ float  g_v[(size_t)MM*DMODEL];
__device__ __half g_attn[(size_t)MM*DMODEL];   // [B,S,D] fp16 (O-proj input)
__device__ __half g_hq[(size_t)MM*DMODEL];     // fp16 copies of inputs
__device__ __half g_hk[(size_t)MM*DMODEL];
__device__ __half g_hv[(size_t)MM*DMODEL];
__device__ __half g_hw[(size_t)4*DMODEL*DMODEL]; // Wq,Wk,Wv,Wo fp16

// ============================================================================
// PTX helpers — ONLY plain-ISA instructions (sm_80-era): cp.async, ldmatrix,
// mma.sync. NO tcgen05 (harness PTX target lacks the 'a' suffix).
// ============================================================================
__device__ __forceinline__ uint32_t s2u(const void* p) {
    uint32_t a;
    asm("{ .reg .u64 t; cvta.to.shared.u64 t, %1; cvt.u32.u64 %0, t; }"
        : "=r"(a) : "l"(p));
    return a;
}

__device__ __forceinline__ void cp16(uint32_t dst, const void* src) {
    asm volatile("cp.async.cg.shared.global [%0], [%1], 16;"
                 :: "r"(dst), "l"(src));
}
__device__ __forceinline__ void cp_commit() {
    asm volatile("cp.async.commit_group;");
}
__device__ __forceinline__ void cp_wait1() {
    asm volatile("cp.async.wait_group 1;" ::: "memory");
}
__device__ __forceinline__ void cp_wait0() {
    asm volatile("cp.async.wait_group 0;" ::: "memory");
}

__device__ __forceinline__ void ldsm4(uint32_t* r, uint32_t a) {
    asm volatile("ldmatrix.sync.aligned.m8n8.x4.shared.b16 {%0,%1,%2,%3}, [%4];"
                 : "=r"(r[0]), "=r"(r[1]), "=r"(r[2]), "=r"(r[3]) : "r"(a));
}

__device__ __forceinline__ void mma16816(float* d, const uint32_t* a,
                                         uint32_t b0, uint32_t b1) {
    asm volatile(
        "mma.sync.aligned.m16n8k16.row.col.f32.f16.f16.f32 "
        "{%0,%1,%2,%3}, {%4,%5,%6,%7}, {%8,%9}, {%0,%1,%2,%3};"
        : "+f"(d[0]), "+f"(d[1]), "+f"(d[2]), "+f"(d[3])
        : "r"(a[0]), "r"(a[1]), "r"(a[2]), "r"(a[3]), "r"(b0), "r"(b1));
}

// ============================================================================
// fp32 -> fp16 conversion (vectorized, n % 4 == 0)
// ============================================================================
__global__ __launch_bounds__(256)
void f2h_kernel(const float* __restrict__ src, __half* __restrict__ dst, int n)
{
    int i = (blockIdx.x * blockDim.x + threadIdx.x) << 2;
    if (i >= n) return;
    float4 v = *(const float4*)(src + i);
    __half2* d = (__half2*)(dst + i);
    d[0] = __floats2half2_rn(v.x, v.y);
    d[1] = __floats2half2_rn(v.z, v.w);
}

// ============================================================================
// HMMA GEMM: C[M,1024](fp32) = A[M,1024](fp16) @ W[1024,1024](fp16)^T + bias
// CTA tile 128x128, K-step 32, 256 thr = 8 warps (2M x 4N), warp tile 64x32.
// Double-buffered smem via cp.async; padded pitch 40 halves (80B) gives
// conflict-free ldmatrix for both operands (row.col, no .trans).
// grid = (1024/128, M/128) = (8, 64).
// ============================================================================
#define GP 40            // smem pitch in halves (80 B): banks 0,20,8,28,16,4,24,12
#define GTILE (128*GP)   // halves per tile buffer (10240 B)

__global__ __launch_bounds__(256)
void gemm_hmma(const __half* __restrict__ A,
               const __half* __restrict__ W,
               const float* __restrict__ bias,
               float* __restrict__ C)
{
    __shared__ __half As[2][GTILE];
    __shared__ __half Bs[2][GTILE];

    const int tid   = threadIdx.x;
    const int wid   = tid >> 5;
    const int lane  = tid & 31;
    const int warpM = wid >> 2;        // 0..1
    const int warpN = wid & 3;         // 0..3
    const int m0 = blockIdx.y * 128;
    const int n0 = blockIdx.x * 128;

    const uint32_t sA = s2u(As);
    const uint32_t sB = s2u(Bs);

    float acc[4][4][4];
#pragma unroll
    for (int i = 0; i < 4; i++)
#pragma unroll
        for (int j = 0; j < 4; j++)
#pragma unroll
            for (int k = 0; k < 4; k++) acc[i][j][k] = 0.f;

    // loader: 512 16B-chunks per operand per step; 2 per thread
    const int lr0 = tid >> 2;          // row for chunk tid
    const int lc0 = tid & 3;           // 16B-chunk within row

#define ISSUE_LOADS(buf, k0)                                                   \
    {                                                                          \
        _Pragma("unroll")                                                      \
        for (int it = 0; it < 2; ++it) {                                       \
            const int r  = lr0 + it * 64;                                      \
            const uint32_t so = (uint32_t)(r * 80 + lc0 * 16);                 \
            cp16(sA + (buf) * (GTILE * 2) + so,                                \
                 A + (size_t)(m0 + r) * DMODEL + (k0) + lc0 * 8);              \
            cp16(sB + (buf) * (GTILE * 2) + so,                                \
                 W + (size_t)(n0 + r) * DMODEL + (k0) + lc0 * 8);              \
        }                                                                      \
        cp_commit();                                                           \
    }

    ISSUE_LOADS(0, 0);

    // ldmatrix lane-address components (loop-invariant)
    const int a_row_in  = (lane & 15);            // row within 16-row frag
    const int a_k8      = (lane >> 4) << 4;       // 0 or 16 bytes (k8 select)
    const int b_nsub    = (lane & 7) + ((lane >> 4) & 1) * 8;
    const int b_k8      = ((lane >> 3) & 1) << 4;

    for (int s = 0; s < 32; ++s) {
        if (s + 1 < 32) { ISSUE_LOADS((s + 1) & 1, (s + 1) * 32); cp_wait1(); }
        else            { cp_wait0(); }
        __syncthreads();

        const uint32_t a_base = sA + (uint32_t)(s & 1) * (GTILE * 2);
        const uint32_t b_base = sB + (uint32_t)(s & 1) * (GTILE * 2);

#pragma unroll
        for (int kk = 0; kk < 2; ++kk) {
            uint32_t ar[4][4];
#pragma unroll
            for (int mf = 0; mf < 4; ++mf) {
                const int row = warpM * 64 + mf * 16 + a_row_in;
                ldsm4(ar[mf], a_base + (uint32_t)(row * 80 + kk * 32 + a_k8));
            }
            uint32_t br[2][4];
#pragma unroll
            for (int nf2 = 0; nf2 < 2; ++nf2) {
                const int nrow = warpN * 32 + nf2 * 16 + b_nsub;
                ldsm4(br[nf2], b_base + (uint32_t)(nrow * 80 + kk * 32 + b_k8));
            }
#pragma unroll
            for (int mf = 0; mf < 4; ++mf)
#pragma unroll
                for (int nf = 0; nf < 4; ++nf)
                    mma16816(acc[mf][nf], ar[mf],
                             br[nf >> 1][(nf & 1) * 2],
                             br[nf >> 1][(nf & 1) * 2 + 1]);
        }
        __syncthreads();
    }

    // epilogue: + bias, fp32 out
    const int rb = m0 + warpM * 64 + (lane >> 2);
    const int cb = n0 + warpN * 32 + (lane & 3) * 2;
#pragma unroll
    for (int nf = 0; nf < 4; ++nf) {
        const int c = cb + nf * 8;
        const float b0 = __ldg(bias + c), b1 = __ldg(bias + c + 1);
#pragma unroll
        for (int mf = 0; mf < 4; ++mf) {
            const int r = rb + mf * 16;
            float2 v0 = make_float2(acc[mf][nf][0] + b0, acc[mf][nf][1] + b1);
            float2 v1 = make_float2(acc[mf][nf][2] + b0, acc[mf][nf][3] + b1);
            *(float2*)(C + (size_t)r * DMODEL + c)       = v0;
            *(float2*)(C + (size_t)(r + 8) * DMODEL + c) = v1;
        }
    }
#undef ISSUE_LOADS
}

// ============================================================================
// Flash attention (causal), fp32 SIMT (unchanged from passing version).
// q/k/v in [B,S,D] fp32 (head h at column h*64). Output [B,S,D] fp16.
// grid=(S/64, B*H), 128 threads.
// ============================================================================
#define FBM 64
#define FBN 64
#define FPAD 65
#define FLASH_SMEM (4 * FBM * FPAD * (int)sizeof(float))   // 66560 B

__global__ __launch_bounds__(128)
void flash_kernel(const float* __restrict__ gq,
                  const float* __restrict__ gk,
                  const float* __restrict__ gv,
                  __half* __restrict__ gout)
{
    extern __shared__ float sm[];
    float* Qs = sm;                   // [64][65]
    float* Ks = Qs + FBM * FPAD;
    float* Vs = Ks + FBM * FPAD;
    float* Ps = Vs + FBM * FPAD;

    const int tid = threadIdx.x;
    const int tx  = tid & 7;
    const int ty  = tid >> 3;
    const int bx  = blockIdx.x;
    const int bh  = blockIdx.y;
    const int q0  = bx * FBM;
    const int b_  = bh >> 4;
    const int h   = bh & (HH - 1);
    const size_t rowbase = (size_t)b_ * SS;
    const int    coloff  = h * DK;

    {
        const float* qptr = gq + (rowbase + q0) * DMODEL + coloff;
        for (int t = tid; t < FBM * 16; t += 128) {
            const int r = t >> 4, c = (t & 15) * 4;
            float4 v = *(const float4*)(qptr + (size_t)r * DMODEL + c);
            Qs[r * FPAD + c + 0] = v.x * 0.125f;
            Qs[r * FPAD + c + 1] = v.y * 0.125f;
            Qs[r * FPAD + c + 2] = v.z * 0.125f;
            Qs[r * FPAD + c + 3] = v.w * 0.125f;
        }
    }

    float m_i[4], l_i[4], acc[4][8];
#pragma unroll
    for (int i = 0; i < 4; i++) {
        m_i[i] = -INFINITY; l_i[i] = 0.f;
#pragma unroll
        for (int j = 0; j < 8; j++) acc[i][j] = 0.f;
    }

    for (int kt = 0; kt <= bx; kt++) {
        const int k0 = kt * FBN;
        __syncthreads();
        {
            const float* kptr = gk + (rowbase + k0) * DMODEL + coloff;
            const float* vptr = gv + (rowbase + k0) * DMODEL + coloff;
            for (int t = tid; t < FBN * 16; t += 128) {
                const int r = t >> 4, c = (t & 15) * 4;
                float4 kv = *(const float4*)(kptr + (size_t)r * DMODEL + c);
                Ks[r*FPAD+c+0]=kv.x; Ks[r*FPAD+c+1]=kv.y;
                Ks[r*FPAD+c+2]=kv.z; Ks[r*FPAD+c+3]=kv.w;
                float4 vv = *(const float4*)(vptr + (size_t)r * DMODEL + c);
                Vs[r*FPAD+c+0]=vv.x; Vs[r*FPAD+c+1]=vv.y;
                Vs[r*FPAD+c+2]=vv.z; Vs[r*FPAD+c+3]=vv.w;
            }
        }
        __syncthreads();

        float s[4][8];
#pragma unroll
        for (int i = 0; i < 4; i++)
#pragma unroll
            for (int j = 0; j < 8; j++) s[i][j] = 0.f;

#pragma unroll 4
        for (int d = 0; d < DK; d++) {
            float qf[4], kf[8];
#pragma unroll
            for (int i = 0; i < 4; i++) qf[i] = Qs[(i * 16 + ty) * FPAD + d];
#pragma unroll
            for (int j = 0; j < 8; j++) kf[j] = Ks[(j * 8 + tx) * FPAD + d];
#pragma unroll
            for (int i = 0; i < 4; i++)
#pragma unroll
                for (int j = 0; j < 8; j++)
                    s[i][j] = fmaf(qf[i], kf[j], s[i][j]);
        }

        if (kt == bx) {
#pragma unroll
            for (int i = 0; i < 4; i++) {
                const int qr = q0 + i * 16 + ty;
#pragma unroll
                for (int j = 0; j < 8; j++) {
                    const int kc = k0 + j * 8 + tx;
                    if (kc > qr) s[i][j] = -INFINITY;
                }
            }
        }

#pragma unroll
        for (int i = 0; i < 4; i++) {
            float mx = s[i][0];
#pragma unroll
            for (int j = 1; j < 8; j++) mx = fmaxf(mx, s[i][j]);
            mx = fmaxf(mx, __shfl_xor_sync(0xffffffffu, mx, 1));
            mx = fmaxf(mx, __shfl_xor_sync(0xffffffffu, mx, 2));
            mx = fmaxf(mx, __shfl_xor_sync(0xffffffffu, mx, 4));
            const float m_new = fmaxf(m_i[i], mx);
            const float scale = __expf(m_i[i] - m_new);
            float ps = 0.f;
#pragma unroll
            for (int j = 0; j < 8; j++) {
                const float p = __expf(s[i][j] - m_new);
                s[i][j] = p;
                ps += p;
            }
            ps += __shfl_xor_sync(0xffffffffu, ps, 1);
            ps += __shfl_xor_sync(0xffffffffu, ps, 2);
            ps += __shfl_xor_sync(0xffffffffu, ps, 4);
            l_i[i] = l_i[i] * scale + ps;
            m_i[i] = m_new;
#pragma unroll
            for (int j = 0; j < 8; j++) acc[i][j] *= scale;
        }

#pragma unroll
        for (int i = 0; i < 4; i++)
#pragma unroll
            for (int j = 0; j < 8; j++)
                Ps[(i * 16 + ty) * FPAD + (j * 8 + tx)] = s[i][j];
        __syncthreads();

#pragma unroll 4
        for (int kk = 0; kk < FBN; kk++) {
            float pf[4], vf[8];
#pragma unroll
            for (int i = 0; i < 4; i++) pf[i] = Ps[(i * 16 + ty) * FPAD + kk];
#pragma unroll
            for (int j = 0; j < 8; j++) vf[j] = Vs[kk * FPAD + j * 8 + tx];
#pragma unroll
            for (int i = 0; i < 4; i++)
#pragma unroll
                for (int j = 0; j < 8; j++)
                    acc[i][j] = fmaf(pf[i], vf[j], acc[i][j]);
        }
    }

#pragma unroll
    for (int i = 0; i < 4; i++) {
        const float inv = 1.0f / l_i[i];
        const int srow = q0 + i * 16 + ty;
        __half* op = gout + (rowbase + srow) * DMODEL + coloff;
#pragma unroll
        for (int j = 0; j < 8; j++)
            op[j * 8 + tx] = __float2half_rn(acc[i][j] * inv);
    }
}

// ============================================================================
// launch
// ============================================================================
extern "C" void kernel_launch(void* const* d_in, const int* in_sizes, int n_in,
                              void* d_out, int out_size)
{
    const float* Q   = (const float*)d_in[0];
    const float* K   = (const float*)d_in[1];
    const float* V   = (const float*)d_in[2];
    // d_in[3] = mask (causal tril; handled analytically)
    const float* W_q = (const float*)d_in[4];
    const float* b_q = (const float*)d_in[5];
    const float* W_k = (const float*)d_in[6];
    const float* b_k = (const float*)d_in[7];
    const float* W_v = (const float*)d_in[8];
    const float* b_v = (const float*)d_in[9];
    const float* W_o = (const float*)d_in[10];
    const float* b_o = (const float*)d_in[11];
    float* out = (float*)d_out;

    float  *gq, *gk, *gv;
    __half *gattn, *hq, *hk, *hv, *hw;
    cudaGetSymbolAddress((void**)&gq,    g_q);
    cudaGetSymbolAddress((void**)&gk,    g_k);
    cudaGetSymbolAddress((void**)&gv,    g_v);
    cudaGetSymbolAddress((void**)&gattn, g_attn);
    cudaGetSymbolAddress((void**)&hq,    g_hq);
    cudaGetSymbolAddress((void**)&hk,    g_hk);
    cudaGetSymbolAddress((void**)&hv,    g_hv);
    cudaGetSymbolAddress((void**)&hw,    g_hw);

    cudaFuncSetAttribute(flash_kernel,
                         cudaFuncAttributeMaxDynamicSharedMemorySize, FLASH_SMEM);

    const int nBig = MM * DMODEL;          // 8,388,608
    const int nW   = DMODEL * DMODEL;      // 1,048,576

    f2h_kernel<<<nBig / 4 / 256, 256>>>(Q,   hq,                  nBig);
    f2h_kernel<<<nBig / 4 / 256, 256>>>(K,   hk,                  nBig);
    f2h_kernel<<<nBig / 4 / 256, 256>>>(V,   hv,                  nBig);
    f2h_kernel<<<nW   / 4 / 256, 256>>>(W_q, hw + 0 * (size_t)nW, nW);
    f2h_kernel<<<nW   / 4 / 256, 256>>>(W_k, hw + 1 * (size_t)nW, nW);
    f2h_kernel<<<nW   / 4 / 256, 256>>>(W_v, hw + 2 * (size_t)nW, nW);
    f2h_kernel<<<nW   / 4 / 256, 256>>>(W_o, hw + 3 * (size_t)nW, nW);

    dim3 ggrid(DMODEL / 128, MM / 128);    // (8, 64)

    gemm_hmma<<<ggrid, 256>>>(hq, hw + 0 * (size_t)nW, b_q, gq);
    gemm_hmma<<<ggrid, 256>>>(hk, hw + 1 * (size_t)nW, b_k, gk);
    gemm_hmma<<<ggrid, 256>>>(hv, hw + 2 * (size_t)nW, b_v, gv);

    flash_kernel<<<dim3(SS / FBM, BB * HH), 128, FLASH_SMEM>>>(gq, gk, gv, gattn);

    gemm_hmma<<<ggrid, 256>>>(gattn, hw + 3 * (size_t)nW, b_o, out);
}

// round 12
// speedup vs baseline: 3.3373x; 3.3373x over previous
#include <cuda_runtime.h>
#include <cuda_fp16.h>
#include <math.h>
#include <stdint.h>

// Problem constants
#define BB 4
#define SS 2048
#define HH 16
#define DMODEL 1024
#define DK 64
#define MM (BB*SS)            // 8192

// ---------------- scratch (__device__ globals: allocation-guard safe) ------
__device__ __half g_hq[(size_t)MM*DMODEL];       // fp16 copies of raw inputs
__device__ __half g_hk[(size_t)MM*DMODEL];
__device__ __half g_hv[(size_t)MM*DMODEL];
__device__ __half g_hw[(size_t)4*DMODEL*DMODEL]; // Wq,Wk,Wv,Wo fp16
__device__ __half g_pq[(size_t)MM*DMODEL];       // projected q (pre-scaled 1/8)
__device__ __half g_pk[(size_t)MM*DMODEL];       // projected k
__device__ __half g_pv[(size_t)MM*DMODEL];       // projected v
__device__ __half g_attn[(size_t)MM*DMODEL];     // attention out [B,S,D] fp16

// ============================================================================
// PTX helpers — plain-ISA only (cp.async / ldmatrix / mma.sync). No tcgen05.
// ============================================================================
__device__ __forceinline__ uint32_t s2u(const void* p) {
    uint32_t a;
    asm("{ .reg .u64 t; cvta.to.shared.u64 t, %1; cvt.u32.u64 %0, t; }"
        : "=r"(a) : "l"(p));
    return a;
}
__device__ __forceinline__ void cp16(uint32_t dst, const void* src) {
    asm volatile("cp.async.cg.shared.global [%0], [%1], 16;" :: "r"(dst), "l"(src));
}
__device__ __forceinline__ void cp_commit() { asm volatile("cp.async.commit_group;"); }
__device__ __forceinline__ void cp_wait1()  { asm volatile("cp.async.wait_group 1;" ::: "memory"); }
__device__ __forceinline__ void cp_wait0()  { asm volatile("cp.async.wait_group 0;" ::: "memory"); }

__device__ __forceinline__ void ldsm4(uint32_t* r, uint32_t a) {
    asm volatile("ldmatrix.sync.aligned.m8n8.x4.shared.b16 {%0,%1,%2,%3}, [%4];"
                 : "=r"(r[0]), "=r"(r[1]), "=r"(r[2]), "=r"(r[3]) : "r"(a));
}
__device__ __forceinline__ void ldsm4t(uint32_t* r, uint32_t a) {
    asm volatile("ldmatrix.sync.aligned.m8n8.x4.trans.shared.b16 {%0,%1,%2,%3}, [%4];"
                 : "=r"(r[0]), "=r"(r[1]), "=r"(r[2]), "=r"(r[3]) : "r"(a));
}
__device__ __forceinline__ void mma16816(float* d, const uint32_t* a,
                                         uint32_t b0, uint32_t b1) {
    asm volatile(
        "mma.sync.aligned.m16n8k16.row.col.f32.f16.f16.f32 "
        "{%0,%1,%2,%3}, {%4,%5,%6,%7}, {%8,%9}, {%0,%1,%2,%3};"
        : "+f"(d[0]), "+f"(d[1]), "+f"(d[2]), "+f"(d[3])
        : "r"(a[0]), "r"(a[1]), "r"(a[2]), "r"(a[3]), "r"(b0), "r"(b1));
}
__device__ __forceinline__ uint32_t packh2(float x, float y) {
    __half2 h = __floats2half2_rn(x, y);
    return *reinterpret_cast<uint32_t*>(&h);
}

// ============================================================================
// fp32 -> fp16 conversion
// ============================================================================
__global__ __launch_bounds__(256)
void f2h_kernel(const float* __restrict__ src, __half* __restrict__ dst, int n)
{
    int i = (blockIdx.x * blockDim.x + threadIdx.x) << 2;
    if (i >= n) return;
    float4 v = *(const float4*)(src + i);
    __half2* d = (__half2*)(dst + i);
    d[0] = __floats2half2_rn(v.x, v.y);
    d[1] = __floats2half2_rn(v.z, v.w);
}

// ============================================================================
// HMMA GEMM core (shared by both gemm kernels): CTA 128x128, K-step 32,
// 8 warps (2Mx4N), warp tile 64x32, double-buffered cp.async, pitch 80B.
// ============================================================================
#define GP 40
#define GTILE (128*GP)

#define GEMM_BODY(Aptr, Wptr)                                                  \
    __shared__ __half As[2][GTILE];                                            \
    __shared__ __half Bs[2][GTILE];                                            \
    const int tid   = threadIdx.x;                                             \
    const int wid   = tid >> 5;                                                \
    const int lane  = tid & 31;                                                \
    const int warpM = wid >> 2;                                                \
    const int warpN = wid & 3;                                                 \
    const int m0 = blockIdx.y * 128;                                           \
    const int n0 = blockIdx.x * 128;                                           \
    const uint32_t sA = s2u(As);                                               \
    const uint32_t sB = s2u(Bs);                                               \
    float acc[4][4][4];                                                        \
    _Pragma("unroll") for (int i = 0; i < 4; i++)                              \
    _Pragma("unroll") for (int j = 0; j < 4; j++)                              \
    _Pragma("unroll") for (int k = 0; k < 4; k++) acc[i][j][k] = 0.f;          \
    const int lr0 = tid >> 2;                                                  \
    const int lc0 = tid & 3;                                                   \
    {   _Pragma("unroll") for (int it = 0; it < 2; ++it) {                     \
            const int r = lr0 + it * 64;                                       \
            const uint32_t so = (uint32_t)(r * 80 + lc0 * 16);                 \
            cp16(sA + so, (Aptr) + (size_t)(m0 + r) * DMODEL + lc0 * 8);       \
            cp16(sB + so, (Wptr) + (size_t)(n0 + r) * DMODEL + lc0 * 8); }     \
        cp_commit(); }                                                         \
    const int a_row_in = (lane & 15);                                          \
    const int a_k8     = (lane >> 4) << 4;                                     \
    const int b_nsub   = (lane & 7) + ((lane >> 4) & 1) * 8;                   \
    const int b_k8     = ((lane >> 3) & 1) << 4;                               \
    for (int s = 0; s < 32; ++s) {                                             \
        if (s + 1 < 32) {                                                      \
            const int k0n = (s + 1) * 32;                                      \
            const uint32_t bo = (uint32_t)((s + 1) & 1) * (GTILE * 2);         \
            _Pragma("unroll") for (int it = 0; it < 2; ++it) {                 \
                const int r = lr0 + it * 64;                                   \
                const uint32_t so = bo + (uint32_t)(r * 80 + lc0 * 16);        \
                cp16(sA + so, (Aptr) + (size_t)(m0 + r) * DMODEL + k0n + lc0 * 8); \
                cp16(sB + so, (Wptr) + (size_t)(n0 + r) * DMODEL + k0n + lc0 * 8); } \
            cp_commit(); cp_wait1();                                           \
        } else cp_wait0();                                                     \
        __syncthreads();                                                       \
        const uint32_t a_base = sA + (uint32_t)(s & 1) * (GTILE * 2);          \
        const uint32_t b_base = sB + (uint32_t)(s & 1) * (GTILE * 2);          \
        _Pragma("unroll") for (int kk = 0; kk < 2; ++kk) {                     \
            uint32_t ar[4][4];                                                 \
            _Pragma("unroll") for (int mf = 0; mf < 4; ++mf) {                 \
                const int row = warpM * 64 + mf * 16 + a_row_in;               \
                ldsm4(ar[mf], a_base + (uint32_t)(row * 80 + kk * 32 + a_k8)); } \
            uint32_t br[2][4];                                                 \
            _Pragma("unroll") for (int nf2 = 0; nf2 < 2; ++nf2) {              \
                const int nrow = warpN * 32 + nf2 * 16 + b_nsub;               \
                ldsm4(br[nf2], b_base + (uint32_t)(nrow * 80 + kk * 32 + b_k8)); } \
            _Pragma("unroll") for (int mf = 0; mf < 4; ++mf)                   \
            _Pragma("unroll") for (int nf = 0; nf < 4; ++nf)                   \
                mma16816(acc[mf][nf], ar[mf],                                  \
                         br[nf >> 1][(nf & 1) * 2],                            \
                         br[nf >> 1][(nf & 1) * 2 + 1]); }                     \
        __syncthreads(); }                                                     \
    const int rb = m0 + warpM * 64 + (lane >> 2);                              \
    const int cb = n0 + warpN * 32 + (lane & 3) * 2;

// ---- QKV projections (fused, fp16 out, q pre-scaled by 1/8) ---------------
__global__ __launch_bounds__(256)
void gemm_qkv(const __half* __restrict__ hq, const __half* __restrict__ hk,
              const __half* __restrict__ hv, const __half* __restrict__ hw,
              const float* __restrict__ bq, const float* __restrict__ bk,
              const float* __restrict__ bv,
              __half* __restrict__ pq, __half* __restrict__ pk,
              __half* __restrict__ pv)
{
    const int z = blockIdx.z;
    const __half* A    = (z == 0) ? hq : (z == 1) ? hk : hv;
    const __half* W    = hw + (size_t)z * DMODEL * DMODEL;
    const float*  bias = (z == 0) ? bq : (z == 1) ? bk : bv;
    __half*       C    = (z == 0) ? pq : (z == 1) ? pk : pv;
    const float scale  = (z == 0) ? 0.125f : 1.0f;

    GEMM_BODY(A, W)

#pragma unroll
    for (int nf = 0; nf < 4; ++nf) {
        const int c = cb + nf * 8;
        const float b0 = __ldg(bias + c), b1 = __ldg(bias + c + 1);
#pragma unroll
        for (int mf = 0; mf < 4; ++mf) {
            const int r = rb + mf * 16;
            __half2 h0 = __floats2half2_rn((acc[mf][nf][0] + b0) * scale,
                                           (acc[mf][nf][1] + b1) * scale);
            __half2 h1 = __floats2half2_rn((acc[mf][nf][2] + b0) * scale,
                                           (acc[mf][nf][3] + b1) * scale);
            *(__half2*)(C + (size_t)r * DMODEL + c)       = h0;
            *(__half2*)(C + (size_t)(r + 8) * DMODEL + c) = h1;
        }
    }
}

// ---- O projection (fp32 out) -----------------------------------------------
__global__ __launch_bounds__(256)
void gemm_hmma(const __half* __restrict__ Ain, const __half* __restrict__ Win,
               const float* __restrict__ bias, float* __restrict__ C)
{
    GEMM_BODY(Ain, Win)

#pragma unroll
    for (int nf = 0; nf < 4; ++nf) {
        const int c = cb + nf * 8;
        const float b0 = __ldg(bias + c), b1 = __ldg(bias + c + 1);
#pragma unroll
        for (int mf = 0; mf < 4; ++mf) {
            const int r = rb + mf * 16;
            *(float2*)(C + (size_t)r * DMODEL + c) =
                make_float2(acc[mf][nf][0] + b0, acc[mf][nf][1] + b1);
            *(float2*)(C + (size_t)(r + 8) * DMODEL + c) =
                make_float2(acc[mf][nf][2] + b0, acc[mf][nf][3] + b1);
        }
    }
}

// ============================================================================
// Tensor-core flash attention (causal). 128 thr = 4 warps; warp owns 16 query
// rows; BM=64, BN=64, Dk=64. Q frags in regs, P reused register-to-register,
// V via ldmatrix.trans. K/V double-buffered via cp.async. Pitch 144B.
// grid = (32, B*H); heavy tiles (large bx) launched first.
// ============================================================================
#define FP 72           // pitch in halves
#define FPB 144         // pitch in bytes
#define FTILEB (64*FP*2)  // 9216 bytes per tile buffer

__global__ __launch_bounds__(128)
void flash_tc(const __half* __restrict__ pq, const __half* __restrict__ pk,
              const __half* __restrict__ pv, __half* __restrict__ gout)
{
    __shared__ __align__(16) __half Qs[64*FP];
    __shared__ __align__(16) __half Ks[2][64*FP];
    __shared__ __align__(16) __half Vs[2][64*FP];

    const int tid  = threadIdx.x;
    const int lane = tid & 31;
    const int wid  = tid >> 5;
    const int bx   = (int)gridDim.x - 1 - (int)blockIdx.x;  // heavy first
    const int bh   = blockIdx.y;
    const int b_   = bh >> 4;
    const int h    = bh & (HH - 1);
    const int q0   = bx * 64;
    const size_t rowbase = (size_t)b_ * SS;
    const int coloff = h * DK;

    const uint32_t uQ = s2u(Qs);
    const uint32_t uK = s2u(Ks);
    const uint32_t uV = s2u(Vs);

    // Q tile load (group 0)
    {
        const __half* qg = pq + (rowbase + q0) * DMODEL + coloff;
#pragma unroll
        for (int it = 0; it < 4; ++it) {
            const int idx = tid + it * 128;
            const int r = idx >> 3, c = idx & 7;
            cp16(uQ + (uint32_t)(r * FPB + c * 16), qg + (size_t)r * DMODEL + c * 8);
        }
        cp_commit();
    }

#define LOAD_KV(kt_, buf_)                                                     \
    {   const __half* kg = pk + (rowbase + (kt_) * 64) * DMODEL + coloff;      \
        const __half* vg = pv + (rowbase + (kt_) * 64) * DMODEL + coloff;      \
        _Pragma("unroll") for (int it = 0; it < 4; ++it) {                     \
            const int idx = tid + it * 128;                                    \
            const int r = idx >> 3, c = idx & 7;                               \
            const uint32_t so = (uint32_t)((buf_) * FTILEB + r * FPB + c * 16);\
            cp16(uK + so, kg + (size_t)r * DMODEL + c * 8);                    \
            cp16(uV + so, vg + (size_t)r * DMODEL + c * 8); }                  \
        cp_commit(); }

    LOAD_KV(0, 0)
    cp_wait1();          // Q done (KV0 may be in flight)
    __syncthreads();

    // Q fragments -> registers (once)
    const int arow = lane & 15;
    const int ak8  = (lane >> 4) << 4;   // bytes
    uint32_t qf[4][4];
#pragma unroll
    for (int j = 0; j < 4; ++j)
        ldsm4(qf[j], uQ + (uint32_t)((wid * 16 + arow) * FPB + j * 32 + ak8));

    float oacc[8][4];
#pragma unroll
    for (int nf = 0; nf < 8; ++nf)
#pragma unroll
        for (int k = 0; k < 4; ++k) oacc[nf][k] = 0.f;
    float m0 = -1e30f, m1 = -1e30f, l0 = 0.f, l1 = 0.f;

    const int lr0 = wid * 16 + (lane >> 2);   // local query row of regs 0,1
    const int lr1 = lr0 + 8;                  // regs 2,3

    for (int kt = 0; kt <= bx; ++kt) {
        if (kt < bx) { LOAD_KV(kt + 1, (kt + 1) & 1) cp_wait1(); }
        else         { cp_wait0(); }
        __syncthreads();

        const uint32_t ukb = uK + (uint32_t)(kt & 1) * FTILEB;
        const uint32_t uvb = uV + (uint32_t)(kt & 1) * FTILEB;

        // ---- S = Q K^T ----
        float s[8][4];
#pragma unroll
        for (int nf = 0; nf < 8; ++nf)
#pragma unroll
            for (int k = 0; k < 4; ++k) s[nf][k] = 0.f;

#pragma unroll
        for (int j = 0; j < 4; ++j) {
#pragma unroll
            for (int nb = 0; nb < 4; ++nb) {
                uint32_t br[4];
                ldsm4(br, ukb + (uint32_t)((nb * 16 + arow) * FPB + j * 32 + ak8));
                mma16816(s[2 * nb],     qf[j], br[0], br[2]);
                mma16816(s[2 * nb + 1], qf[j], br[1], br[3]);
            }
        }

        // ---- causal mask (diagonal tile only) ----
        if (kt == bx) {
#pragma unroll
            for (int nf = 0; nf < 8; ++nf) {
                const int kc0 = nf * 8 + (lane & 3) * 2;
                const int kc1 = kc0 + 1;
                if (kc0 > lr0) s[nf][0] = -1e30f;
                if (kc1 > lr0) s[nf][1] = -1e30f;
                if (kc0 > lr1) s[nf][2] = -1e30f;
                if (kc1 > lr1) s[nf][3] = -1e30f;
            }
        }

        // ---- online softmax (fragment layout) ----
        float mx0 = -1e30f, mx1 = -1e30f;
#pragma unroll
        for (int nf = 0; nf < 8; ++nf) {
            mx0 = fmaxf(mx0, fmaxf(s[nf][0], s[nf][1]));
            mx1 = fmaxf(mx1, fmaxf(s[nf][2], s[nf][3]));
        }
        mx0 = fmaxf(mx0, __shfl_xor_sync(0xffffffffu, mx0, 1));
        mx0 = fmaxf(mx0, __shfl_xor_sync(0xffffffffu, mx0, 2));
        mx1 = fmaxf(mx1, __shfl_xor_sync(0xffffffffu, mx1, 1));
        mx1 = fmaxf(mx1, __shfl_xor_sync(0xffffffffu, mx1, 2));

        const float mn0 = fmaxf(m0, mx0);
        const float mn1 = fmaxf(m1, mx1);
        const float a0 = __expf(m0 - mn0);
        const float a1 = __expf(m1 - mn1);
        float sum0 = 0.f, sum1 = 0.f;
#pragma unroll
        for (int nf = 0; nf < 8; ++nf) {
            s[nf][0] = __expf(s[nf][0] - mn0);
            s[nf][1] = __expf(s[nf][1] - mn0);
            s[nf][2] = __expf(s[nf][2] - mn1);
            s[nf][3] = __expf(s[nf][3] - mn1);
            sum0 += s[nf][0] + s[nf][1];
            sum1 += s[nf][2] + s[nf][3];
        }
        sum0 += __shfl_xor_sync(0xffffffffu, sum0, 1);
        sum0 += __shfl_xor_sync(0xffffffffu, sum0, 2);
        sum1 += __shfl_xor_sync(0xffffffffu, sum1, 1);
        sum1 += __shfl_xor_sync(0xffffffffu, sum1, 2);
        l0 = l0 * a0 + sum0;  m0 = mn0;
        l1 = l1 * a1 + sum1;  m1 = mn1;
#pragma unroll
        for (int nf = 0; nf < 8; ++nf) {
            oacc[nf][0] *= a0; oacc[nf][1] *= a0;
            oacc[nf][2] *= a1; oacc[nf][3] *= a1;
        }

        // ---- P (fp16 A-frags, register reuse) ----
        uint32_t pa[4][4];
#pragma unroll
        for (int j = 0; j < 4; ++j) {
            pa[j][0] = packh2(s[2 * j][0],     s[2 * j][1]);
            pa[j][1] = packh2(s[2 * j][2],     s[2 * j][3]);
            pa[j][2] = packh2(s[2 * j + 1][0], s[2 * j + 1][1]);
            pa[j][3] = packh2(s[2 * j + 1][2], s[2 * j + 1][3]);
        }

        // ---- O += P V  (V via ldmatrix.trans) ----
#pragma unroll
        for (int j = 0; j < 4; ++j) {
#pragma unroll
            for (int db = 0; db < 4; ++db) {
                uint32_t bv[4];
                ldsm4t(bv, uvb + (uint32_t)((j * 16 + arow) * FPB
                                            + (db * 16 + (lane >> 4) * 8) * 2));
                mma16816(oacc[2 * db],     pa[j], bv[0], bv[1]);
                mma16816(oacc[2 * db + 1], pa[j], bv[2], bv[3]);
            }
        }
        __syncthreads();
    }

    // ---- epilogue: normalize, write fp16 [B,S,D] ----
    const float inv0 = 1.0f / l0;
    const float inv1 = 1.0f / l1;
    const size_t gr0 = rowbase + q0 + (size_t)lr0;
    const size_t gr1 = gr0 + 8;
#pragma unroll
    for (int nf = 0; nf < 8; ++nf) {
        const int col = coloff + nf * 8 + (lane & 3) * 2;
        *(__half2*)(gout + gr0 * DMODEL + col) =
            __floats2half2_rn(oacc[nf][0] * inv0, oacc[nf][1] * inv0);
        *(__half2*)(gout + gr1 * DMODEL + col) =
            __floats2half2_rn(oacc[nf][2] * inv1, oacc[nf][3] * inv1);
    }
#undef LOAD_KV
}

// ============================================================================
// launch
// ============================================================================
extern "C" void kernel_launch(void* const* d_in, const int* in_sizes, int n_in,
                              void* d_out, int out_size)
{
    const float* Q   = (const float*)d_in[0];
    const float* K   = (const float*)d_in[1];
    const float* V   = (const float*)d_in[2];
    // d_in[3] = mask (causal tril; handled analytically)
    const float* W_q = (const float*)d_in[4];
    const float* b_q = (const float*)d_in[5];
    const float* W_k = (const float*)d_in[6];
    const float* b_k = (const float*)d_in[7];
    const float* W_v = (const float*)d_in[8];
    const float* b_v = (const float*)d_in[9];
    const float* W_o = (const float*)d_in[10];
    const float* b_o = (const float*)d_in[11];
    float* out = (float*)d_out;

    __half *hq, *hk, *hv, *hw, *pq, *pk, *pv, *gattn;
    cudaGetSymbolAddress((void**)&hq,    g_hq);
    cudaGetSymbolAddress((void**)&hk,    g_hk);
    cudaGetSymbolAddress((void**)&hv,    g_hv);
    cudaGetSymbolAddress((void**)&hw,    g_hw);
    cudaGetSymbolAddress((void**)&pq,    g_pq);
    cudaGetSymbolAddress((void**)&pk,    g_pk);
    cudaGetSymbolAddress((void**)&pv,    g_pv);
    cudaGetSymbolAddress((void**)&gattn, g_attn);

    const int nBig = MM * DMODEL;          // 8,388,608
    const int nW   = DMODEL * DMODEL;      // 1,048,576

    f2h_kernel<<<nBig / 4 / 256, 256>>>(Q,   hq,                  nBig);
    f2h_kernel<<<nBig / 4 / 256, 256>>>(K,   hk,                  nBig);
    f2h_kernel<<<nBig / 4 / 256, 256>>>(V,   hv,                  nBig);
    f2h_kernel<<<nW   / 4 / 256, 256>>>(W_q, hw + 0 * (size_t)nW, nW);
    f2h_kernel<<<nW   / 4 / 256, 256>>>(W_k, hw + 1 * (size_t)nW, nW);
    f2h_kernel<<<nW   / 4 / 256, 256>>>(W_v, hw + 2 * (size_t)nW, nW);
    f2h_kernel<<<nW   / 4 / 256, 256>>>(W_o, hw + 3 * (size_t)nW, nW);

    // fused QKV projections (fp16 out; q pre-scaled by 1/sqrt(Dk))
    gemm_qkv<<<dim3(DMODEL / 128, MM / 128, 3), 256>>>(
        hq, hk, hv, hw, b_q, b_k, b_v, pq, pk, pv);

    // tensor-core causal flash attention
    flash_tc<<<dim3(SS / 64, BB * HH), 128>>>(pq, pk, pv, gattn);

    // O projection (fp32 out)
    gemm_hmma<<<dim3(DMODEL / 128, MM / 128), 256>>>(
        gattn, hw + 3 * (size_t)nW, b_o, out);
}